// round 4
// baseline (speedup 1.0000x reference)
#include <cuda_runtime.h>
#include <math.h>

// ---------------- problem constants ----------------
#define Bv   4
#define Rv   4
#define Nv   4096
#define Mv   64
#define KNv  12288
#define BRv  16
#define P1   196608
#define P2   1024
#define Fv   512
#define TILES2 1536          // P1 / 128
#define TPB2   96            // KN / 128 tiles per br

// ---------------- device scratch ----------------
__device__ int   d_topk[Bv * Nv * 3];
__device__ float d_csum[Bv * 2 * Mv];
__device__ float d_ccnt[Bv * Mv];
__device__ float d_nrot[BRv * 2 * Mv];
__device__ float d_g[130 * P2];
__device__ float d_fcol0[BRv * 128];
__device__ float d_A[256 * P2];
__device__ float d_B2[256 * P2];
__device__ float d_C2[512 * P2];
__device__ float d_D2[512 * P2];

// ---------------- packed f32x2 helpers ----------------
__device__ __forceinline__ unsigned long long ffma2(unsigned long long a,
                                                    unsigned long long b,
                                                    unsigned long long c) {
    unsigned long long d;
    asm("fma.rn.f32x2 %0, %1, %2, %3;" : "=l"(d) : "l"(a), "l"(b), "l"(c));
    return d;
}
__device__ __forceinline__ unsigned long long pack2(float lo, float hi) {
    unsigned long long r;
    asm("mov.b64 %0, {%1, %2};" : "=l"(r) : "f"(lo), "f"(hi));
    return r;
}
__device__ __forceinline__ float lo2(unsigned long long a) { return __uint_as_float((unsigned)a); }
__device__ __forceinline__ float hi2(unsigned long long a) { return __uint_as_float((unsigned)(a >> 32)); }

__device__ __forceinline__ void rot_cs(int r, float& c, float& s) {
    float th = 6.2831855f * (float)r * 0.25f;
    c = cosf(th);
    s = sinf(th);
}

// ---------------- K0 ----------------
__global__ void k_init() {
    int i = blockIdx.x * 256 + threadIdx.x;
    if (i < Bv * 2 * Mv) d_csum[i] = 0.f;
    if (i < Bv * Mv)     d_ccnt[i] = 0.f;
    if (i < 130 * P2)    d_g[i]    = 0.f;
}

// ---------------- K1: top-3 + cluster accumulation ----------
__global__ void k_topk(const float* __restrict__ x, const float* __restrict__ node) {
    int idx = blockIdx.x * 256 + threadIdx.x;
    if (idx >= Bv * Nv) return;
    int b = idx >> 12, n = idx & (Nv - 1);
    float x0 = x[b * 2 * Nv + n];
    float x1 = x[b * 2 * Nv + Nv + n];
    float d0 = 3.4e38f, d1 = 3.4e38f, d2 = 3.4e38f;
    int   i0 = 0, i1 = 0, i2 = 0;
    #pragma unroll
    for (int m = 0; m < Mv; m++) {
        float dx = x0 - __ldg(&node[b * 2 * Mv + m]);
        float dy = x1 - __ldg(&node[b * 2 * Mv + Mv + m]);
        float d = dx * dx + dy * dy;
        if (d < d0)      { d2 = d1; i2 = i1; d1 = d0; i1 = i0; d0 = d; i0 = m; }
        else if (d < d1) { d2 = d1; i2 = i1; d1 = d;  i1 = m; }
        else if (d < d2) { d2 = d;  i2 = m; }
    }
    int o = idx * 3;
    d_topk[o] = i0; d_topk[o + 1] = i1; d_topk[o + 2] = i2;
    atomicAdd(&d_csum[b * 2 * Mv + i0],      x0);
    atomicAdd(&d_csum[b * 2 * Mv + Mv + i0], x1);
    atomicAdd(&d_ccnt[b * Mv + i0], 1.f);
    atomicAdd(&d_csum[b * 2 * Mv + i1],      x0);
    atomicAdd(&d_csum[b * 2 * Mv + Mv + i1], x1);
    atomicAdd(&d_ccnt[b * Mv + i1], 1.f);
    atomicAdd(&d_csum[b * 2 * Mv + i2],      x0);
    atomicAdd(&d_csum[b * 2 * Mv + Mv + i2], x1);
    atomicAdd(&d_ccnt[b * Mv + i2], 1.f);
}

// ---------------- K2 ----------------
__global__ void k_nodes() {
    int idx = threadIdx.x;
    int b = idx >> 6, m = idx & 63;
    float cnt = d_ccnt[b * Mv + m];
    float inv = 1.f / (cnt + 1e-5f);
    float m0 = d_csum[b * 2 * Mv + m]      * inv;
    float m1 = d_csum[b * 2 * Mv + Mv + m] * inv;
    #pragma unroll
    for (int r = 0; r < Rv; r++) {
        float c, s; rot_cs(r, c, s);
        float n0 = c * m0 - s * m1;
        float n1 = s * m0 + c * m1;
        int br = b * Rv + r;
        d_nrot[(br * 2 + 0) * Mv + m] = n0;
        d_nrot[(br * 2 + 1) * Mv + m] = n1;
        d_g[0 * P2 + br * Mv + m] = n0;
        d_g[1 * P2 + br * Mv + m] = n1;
    }
}

// ---------------- fused fp block (128-col tiles, 512 threads) --------------
// smem layout (float offsets)
#define SW0  0          // 128
#define SB0  128        // 64
#define SB1  192        // 64
#define SB2  256        // 128
#define SB3  384        // 128
#define SW1  512        // [64k][64o]   -> 4608
#define SXS  4608       // [2][128]     -> 4864
#define SMS  4864       // int[128]     -> 4992
#define SBA  4992       // [64k][128c]  -> 13184
#define SBB  13184      // [64k][128c]  -> 21376
#define SBC  21376      // [64k][128c]  -> 29568
#define SW2  29568      // [64k][128o]  -> 37760
#define SW3  37760      // [130k][128o] -> 54400
#define SMEM_FLOATS 54400

__global__ void __launch_bounds__(512, 1) k_fp(
    const float* __restrict__ x,
    const float* __restrict__ W0, const float* __restrict__ b0,
    const float* __restrict__ W1, const float* __restrict__ b1,
    const float* __restrict__ W2, const float* __restrict__ b2,
    const float* __restrict__ W3, const float* __restrict__ b3)
{
    extern __shared__ float sm[];
    const int tid = threadIdx.x;

    for (int i = tid; i < 128; i += 512) sm[SW0 + i] = W0[i];
    for (int i = tid; i < 64;  i += 512) { sm[SB0 + i] = b0[i]; sm[SB1 + i] = b1[i]; }
    for (int i = tid; i < 128; i += 512) { sm[SB2 + i] = b2[i]; sm[SB3 + i] = b3[i]; }
    for (int i = tid; i < 4096; i += 512) { int o = i & 63,  k = i >> 6; sm[SW1 + k * 64  + o] = W1[o * 64  + k]; }
    for (int i = tid; i < 8192; i += 512) { int o = i & 127, k = i >> 7; sm[SW2 + k * 128 + o] = W2[o * 64  + k]; }
    for (int i = tid; i < 130 * 128; i += 512) { int o = i & 127, k = i >> 7; sm[SW3 + k * 128 + o] = W3[o * 130 + k]; }
    __syncthreads();

    int* ms = (int*)(sm + SMS);
    const int og = tid >> 4;            // 0..31
    const int cg = tid & 15;            // 0..15
    const int p0 = cg * 8;              // 8 of 128 columns per thread

    for (int t = blockIdx.x; t < TILES2; t += gridDim.x) {
        int br = t / TPB2; int tloc = t - br * TPB2; int kn0 = tloc * 128;
        int b = br >> 2, r = br & 3;

        // ---- P0: xdec prologue ----
        if (tid < 128) {
            int kn = kn0 + tid; int k = kn >> 12; int n = kn & (Nv - 1);
            float x0 = x[b * 2 * Nv + n], x1 = x[b * 2 * Nv + Nv + n];
            float c, s; rot_cs(r, c, s);
            float xr0 = c * x0 - s * x1;
            float xr1 = s * x0 + c * x1;
            int m = d_topk[(b * Nv + n) * 3 + k];
            sm[SXS + tid]       = xr0 - d_nrot[(br * 2 + 0) * Mv + m];
            sm[SXS + 128 + tid] = xr1 - d_nrot[(br * 2 + 1) * Mv + m];
            ms[tid] = m;
        }
        __syncthreads();

        // ---- L0: 64 x 128, K=2 ----
        {
            int o0 = og * 2;
            #pragma unroll
            for (int i = 0; i < 2; i++) {
                int o = o0 + i;
                float w0 = sm[SW0 + o * 2], w1 = sm[SW0 + o * 2 + 1], bb = sm[SB0 + o];
                #pragma unroll
                for (int j = 0; j < 8; j++) {
                    int p = p0 + j;
                    float v = fmaf(w0, sm[SXS + p], fmaf(w1, sm[SXS + 128 + p], bb));
                    sm[SBA + o * 128 + p] = fmaxf(v, 0.f);
                }
            }
        }
        __syncthreads();

        // ---- L1: 64 x 128, K=64 (bA -> bB) ----
        {
            int o0 = og * 2;
            unsigned long long acc[2][4];
            #pragma unroll
            for (int i = 0; i < 2; i++)
                #pragma unroll
                for (int j = 0; j < 4; j++) acc[i][j] = 0ull;
            #pragma unroll 4
            for (int kk = 0; kk < 64; kk++) {
                float2 w = *(const float2*)&sm[SW1 + kk * 64 + o0];
                unsigned long long w0d = pack2(w.x, w.x);
                unsigned long long w1d = pack2(w.y, w.y);
                ulonglong2 a01 = *(const ulonglong2*)&sm[SBA + kk * 128 + p0];
                ulonglong2 a23 = *(const ulonglong2*)&sm[SBA + kk * 128 + p0 + 4];
                acc[0][0] = ffma2(w0d, a01.x, acc[0][0]); acc[0][1] = ffma2(w0d, a01.y, acc[0][1]);
                acc[0][2] = ffma2(w0d, a23.x, acc[0][2]); acc[0][3] = ffma2(w0d, a23.y, acc[0][3]);
                acc[1][0] = ffma2(w1d, a01.x, acc[1][0]); acc[1][1] = ffma2(w1d, a01.y, acc[1][1]);
                acc[1][2] = ffma2(w1d, a23.x, acc[1][2]); acc[1][3] = ffma2(w1d, a23.y, acc[1][3]);
            }
            #pragma unroll
            for (int i = 0; i < 2; i++) {
                int o = o0 + i; float bv = sm[SB1 + o];
                #pragma unroll
                for (int j = 0; j < 4; j++) {
                    float vl = fmaxf(lo2(acc[i][j]) + bv, 0.f);
                    float vh = fmaxf(hi2(acc[i][j]) + bv, 0.f);
                    *(float2*)&sm[SBB + o * 128 + p0 + 2 * j] = make_float2(vl, vh);
                }
            }
        }
        __syncthreads();

        // ---- L2: 128 x 128, K=64 (bB -> bA low / bC high) ----
        {
            int o0 = og * 4;
            unsigned long long acc[4][4];
            #pragma unroll
            for (int i = 0; i < 4; i++)
                #pragma unroll
                for (int j = 0; j < 4; j++) acc[i][j] = 0ull;
            #pragma unroll 4
            for (int kk = 0; kk < 64; kk++) {
                float4 w = *(const float4*)&sm[SW2 + kk * 128 + o0];
                unsigned long long w0d = pack2(w.x, w.x), w1d = pack2(w.y, w.y);
                unsigned long long w2d = pack2(w.z, w.z), w3d = pack2(w.w, w.w);
                ulonglong2 a01 = *(const ulonglong2*)&sm[SBB + kk * 128 + p0];
                ulonglong2 a23 = *(const ulonglong2*)&sm[SBB + kk * 128 + p0 + 4];
                acc[0][0] = ffma2(w0d, a01.x, acc[0][0]); acc[0][1] = ffma2(w0d, a01.y, acc[0][1]);
                acc[0][2] = ffma2(w0d, a23.x, acc[0][2]); acc[0][3] = ffma2(w0d, a23.y, acc[0][3]);
                acc[1][0] = ffma2(w1d, a01.x, acc[1][0]); acc[1][1] = ffma2(w1d, a01.y, acc[1][1]);
                acc[1][2] = ffma2(w1d, a23.x, acc[1][2]); acc[1][3] = ffma2(w1d, a23.y, acc[1][3]);
                acc[2][0] = ffma2(w2d, a01.x, acc[2][0]); acc[2][1] = ffma2(w2d, a01.y, acc[2][1]);
                acc[2][2] = ffma2(w2d, a23.x, acc[2][2]); acc[2][3] = ffma2(w2d, a23.y, acc[2][3]);
                acc[3][0] = ffma2(w3d, a01.x, acc[3][0]); acc[3][1] = ffma2(w3d, a01.y, acc[3][1]);
                acc[3][2] = ffma2(w3d, a23.x, acc[3][2]); acc[3][3] = ffma2(w3d, a23.y, acc[3][3]);
            }
            float* dst = (o0 < 64) ? (sm + SBA + o0 * 128) : (sm + SBC + (o0 - 64) * 128);
            #pragma unroll
            for (int i = 0; i < 4; i++) {
                float bv = sm[SB2 + o0 + i];
                #pragma unroll
                for (int j = 0; j < 4; j++) {
                    float vl = fmaxf(lo2(acc[i][j]) + bv, 0.f);
                    float vh = fmaxf(hi2(acc[i][j]) + bv, 0.f);
                    *(float2*)&dst[i * 128 + p0 + 2 * j] = make_float2(vl, vh);
                }
            }
        }
        __syncthreads();

        // ---- L3: 128 x 128, K=130 -> scatter-max ----
        {
            int o0 = og * 4;
            unsigned long long acc[4][4];
            #pragma unroll
            for (int i = 0; i < 4; i++)
                #pragma unroll
                for (int j = 0; j < 4; j++) acc[i][j] = 0ull;
            #pragma unroll
            for (int k = 0; k < 2; k++) {
                float4 w = *(const float4*)&sm[SW3 + k * 128 + o0];
                unsigned long long w0d = pack2(w.x, w.x), w1d = pack2(w.y, w.y);
                unsigned long long w2d = pack2(w.z, w.z), w3d = pack2(w.w, w.w);
                ulonglong2 a01 = *(const ulonglong2*)&sm[SXS + k * 128 + p0];
                ulonglong2 a23 = *(const ulonglong2*)&sm[SXS + k * 128 + p0 + 4];
                acc[0][0] = ffma2(w0d, a01.x, acc[0][0]); acc[0][1] = ffma2(w0d, a01.y, acc[0][1]);
                acc[0][2] = ffma2(w0d, a23.x, acc[0][2]); acc[0][3] = ffma2(w0d, a23.y, acc[0][3]);
                acc[1][0] = ffma2(w1d, a01.x, acc[1][0]); acc[1][1] = ffma2(w1d, a01.y, acc[1][1]);
                acc[1][2] = ffma2(w1d, a23.x, acc[1][2]); acc[1][3] = ffma2(w1d, a23.y, acc[1][3]);
                acc[2][0] = ffma2(w2d, a01.x, acc[2][0]); acc[2][1] = ffma2(w2d, a01.y, acc[2][1]);
                acc[2][2] = ffma2(w2d, a23.x, acc[2][2]); acc[2][3] = ffma2(w2d, a23.y, acc[2][3]);
                acc[3][0] = ffma2(w3d, a01.x, acc[3][0]); acc[3][1] = ffma2(w3d, a01.y, acc[3][1]);
                acc[3][2] = ffma2(w3d, a23.x, acc[3][2]); acc[3][3] = ffma2(w3d, a23.y, acc[3][3]);
            }
            #pragma unroll 4
            for (int kk = 0; kk < 64; kk++) {                  // h3 rows 0-63 in bA
                float4 w = *(const float4*)&sm[SW3 + (2 + kk) * 128 + o0];
                unsigned long long w0d = pack2(w.x, w.x), w1d = pack2(w.y, w.y);
                unsigned long long w2d = pack2(w.z, w.z), w3d = pack2(w.w, w.w);
                ulonglong2 a01 = *(const ulonglong2*)&sm[SBA + kk * 128 + p0];
                ulonglong2 a23 = *(const ulonglong2*)&sm[SBA + kk * 128 + p0 + 4];
                acc[0][0] = ffma2(w0d, a01.x, acc[0][0]); acc[0][1] = ffma2(w0d, a01.y, acc[0][1]);
                acc[0][2] = ffma2(w0d, a23.x, acc[0][2]); acc[0][3] = ffma2(w0d, a23.y, acc[0][3]);
                acc[1][0] = ffma2(w1d, a01.x, acc[1][0]); acc[1][1] = ffma2(w1d, a01.y, acc[1][1]);
                acc[1][2] = ffma2(w1d, a23.x, acc[1][2]); acc[1][3] = ffma2(w1d, a23.y, acc[1][3]);
                acc[2][0] = ffma2(w2d, a01.x, acc[2][0]); acc[2][1] = ffma2(w2d, a01.y, acc[2][1]);
                acc[2][2] = ffma2(w2d, a23.x, acc[2][2]); acc[2][3] = ffma2(w2d, a23.y, acc[2][3]);
                acc[3][0] = ffma2(w3d, a01.x, acc[3][0]); acc[3][1] = ffma2(w3d, a01.y, acc[3][1]);
                acc[3][2] = ffma2(w3d, a23.x, acc[3][2]); acc[3][3] = ffma2(w3d, a23.y, acc[3][3]);
            }
            #pragma unroll 4
            for (int kk = 0; kk < 64; kk++) {                  // h3 rows 64-127 in bC
                float4 w = *(const float4*)&sm[SW3 + (66 + kk) * 128 + o0];
                unsigned long long w0d = pack2(w.x, w.x), w1d = pack2(w.y, w.y);
                unsigned long long w2d = pack2(w.z, w.z), w3d = pack2(w.w, w.w);
                ulonglong2 a01 = *(const ulonglong2*)&sm[SBC + kk * 128 + p0];
                ulonglong2 a23 = *(const ulonglong2*)&sm[SBC + kk * 128 + p0 + 4];
                acc[0][0] = ffma2(w0d, a01.x, acc[0][0]); acc[0][1] = ffma2(w0d, a01.y, acc[0][1]);
                acc[0][2] = ffma2(w0d, a23.x, acc[0][2]); acc[0][3] = ffma2(w0d, a23.y, acc[0][3]);
                acc[1][0] = ffma2(w1d, a01.x, acc[1][0]); acc[1][1] = ffma2(w1d, a01.y, acc[1][1]);
                acc[1][2] = ffma2(w1d, a23.x, acc[1][2]); acc[1][3] = ffma2(w1d, a23.y, acc[1][3]);
                acc[2][0] = ffma2(w2d, a01.x, acc[2][0]); acc[2][1] = ffma2(w2d, a01.y, acc[2][1]);
                acc[2][2] = ffma2(w2d, a23.x, acc[2][2]); acc[2][3] = ffma2(w2d, a23.y, acc[2][3]);
                acc[3][0] = ffma2(w3d, a01.x, acc[3][0]); acc[3][1] = ffma2(w3d, a01.y, acc[3][1]);
                acc[3][2] = ffma2(w3d, a23.x, acc[3][2]); acc[3][3] = ffma2(w3d, a23.y, acc[3][3]);
            }
            // epilogue: bias + relu + scatter-max
            int mc[8];
            #pragma unroll
            for (int j = 0; j < 8; j++) mc[j] = ms[p0 + j];
            #pragma unroll
            for (int i = 0; i < 4; i++) {
                int o = o0 + i; float bv = sm[SB3 + o];
                #pragma unroll
                for (int j = 0; j < 4; j++) {
                    float vl = fmaxf(lo2(acc[i][j]) + bv, 0.f);
                    float vh = fmaxf(hi2(acc[i][j]) + bv, 0.f);
                    atomicMax((unsigned*)&d_g[(2 + o) * P2 + br * Mv + mc[2 * j]],     __float_as_uint(vl));
                    atomicMax((unsigned*)&d_g[(2 + o) * P2 + br * Mv + mc[2 * j + 1]], __float_as_uint(vh));
                    if (tloc == 0 && cg == 0 && j == 0)
                        d_fcol0[br * 128 + o] = vl;   // feat[:, :, 0]
                }
            }
        }
        __syncthreads();
    }
}

// ---------------- K5: empty-cluster fallback ----------------
__global__ void k_fix() {
    int idx = blockIdx.x * 256 + threadIdx.x;
    int m = idx & 63; int c = (idx >> 6) & 127; int br = idx >> 13;
    int b = br >> 2;
    if (d_ccnt[b * Mv + m] == 0.f)
        d_g[(2 + c) * P2 + br * Mv + m] = d_fcol0[br * 128 + c];
}

// ---------------- gp GEMM + bias + ReLU (col-paired FFMA2) -----------------
__global__ void __launch_bounds__(256) k_gemm(
    const float* __restrict__ W, const float* __restrict__ bias,
    const float* __restrict__ in1, int C1,
    const float* __restrict__ in2, int C2,
    float* __restrict__ out, int P)
{
    __shared__ __align__(16) float Wsh[16][68];
    __shared__ __align__(16) float Ish[16][68];
    const int C = C1 + C2;
    const int col0 = blockIdx.x * 64, ob0 = blockIdx.y * 64;
    const int tid = threadIdx.x;
    const int o0 = (tid >> 3) * 2, p0 = (tid & 7) * 8;
    unsigned long long acc[2][4];
    #pragma unroll
    for (int i = 0; i < 2; i++)
        #pragma unroll
        for (int j = 0; j < 4; j++) acc[i][j] = 0ull;

    for (int k0 = 0; k0 < C; k0 += 16) {
        #pragma unroll
        for (int q = 0; q < 4; q++) {
            int l = tid * 4 + q; int oo = l >> 4, kk = l & 15;
            int c = k0 + kk;
            Wsh[kk][oo] = (c < C) ? W[(ob0 + oo) * C + c] : 0.f;
        }
        #pragma unroll
        for (int q = 0; q < 4; q++) {
            int l = tid * 4 + q; int kk = l >> 6, cc = l & 63;
            int c = k0 + kk;
            float v = 0.f;
            if (c < C1)      v = in1[c * P + col0 + cc];
            else if (c < C)  v = in2[(c - C1) * P + col0 + cc];
            Ish[kk][cc] = v;
        }
        __syncthreads();
        #pragma unroll
        for (int kk = 0; kk < 16; kk++) {
            float2 w = *(const float2*)&Wsh[kk][o0];
            unsigned long long w0d = pack2(w.x, w.x);
            unsigned long long w1d = pack2(w.y, w.y);
            ulonglong2 a01 = *(const ulonglong2*)&Ish[kk][p0];
            ulonglong2 a23 = *(const ulonglong2*)&Ish[kk][p0 + 4];
            acc[0][0] = ffma2(w0d, a01.x, acc[0][0]); acc[0][1] = ffma2(w0d, a01.y, acc[0][1]);
            acc[0][2] = ffma2(w0d, a23.x, acc[0][2]); acc[0][3] = ffma2(w0d, a23.y, acc[0][3]);
            acc[1][0] = ffma2(w1d, a01.x, acc[1][0]); acc[1][1] = ffma2(w1d, a01.y, acc[1][1]);
            acc[1][2] = ffma2(w1d, a23.x, acc[1][2]); acc[1][3] = ffma2(w1d, a23.y, acc[1][3]);
        }
        __syncthreads();
    }
    #pragma unroll
    for (int i = 0; i < 2; i++) {
        int o = ob0 + o0 + i;
        float bv = bias[o];
        #pragma unroll
        for (int j = 0; j < 4; j++) {
            float vl = fmaxf(lo2(acc[i][j]) + bv, 0.f);
            float vh = fmaxf(hi2(acc[i][j]) + bv, 0.f);
            *(float2*)&out[o * P + col0 + p0 + 2 * j] = make_float2(vl, vh);
        }
    }
}

// ---------------- K6: final max over (r, m) ----------------
__global__ void k_reduce(float* __restrict__ out) {
    int idx = blockIdx.x * 256 + threadIdx.x;
    int b = idx >> 9, f = idx & 511;
    const float* src = &d_D2[f * P2 + b * 256];
    float v = 0.f;
    #pragma unroll 8
    for (int j = 0; j < 256; j++) v = fmaxf(v, src[j]);
    out[b * Fv + f] = v;
}

// ---------------- host launcher ----------------
extern "C" void kernel_launch(void* const* d_in, const int* in_sizes, int n_in,
                              void* d_out, int out_size) {
    const float* x    = (const float*)d_in[0];
    const float* node = (const float*)d_in[2];
    const float* fpW0 = (const float*)d_in[4];  const float* fpb0 = (const float*)d_in[5];
    const float* fpW1 = (const float*)d_in[6];  const float* fpb1 = (const float*)d_in[7];
    const float* fpW2 = (const float*)d_in[8];  const float* fpb2 = (const float*)d_in[9];
    const float* fpW3 = (const float*)d_in[10]; const float* fpb3 = (const float*)d_in[11];
    const float* gpW0 = (const float*)d_in[12]; const float* gpb0 = (const float*)d_in[13];
    const float* gpW1 = (const float*)d_in[14]; const float* gpb1 = (const float*)d_in[15];
    const float* gpW2 = (const float*)d_in[16]; const float* gpb2 = (const float*)d_in[17];
    const float* gpW3 = (const float*)d_in[18]; const float* gpb3 = (const float*)d_in[19];

    float *p_g, *p_A, *p_B2, *p_C2, *p_D2;
    cudaGetSymbolAddress((void**)&p_g,  d_g);
    cudaGetSymbolAddress((void**)&p_A,  d_A);
    cudaGetSymbolAddress((void**)&p_B2, d_B2);
    cudaGetSymbolAddress((void**)&p_C2, d_C2);
    cudaGetSymbolAddress((void**)&p_D2, d_D2);

    cudaFuncSetAttribute(k_fp, cudaFuncAttributeMaxDynamicSharedMemorySize,
                         SMEM_FLOATS * 4);

    k_init<<<(130 * P2 + 255) / 256, 256>>>();
    k_topk<<<(Bv * Nv) / 256, 256>>>(x, node);
    k_nodes<<<1, 256>>>();

    k_fp<<<148, 512, SMEM_FLOATS * 4>>>(x, fpW0, fpb0, fpW1, fpb1,
                                        fpW2, fpb2, fpW3, fpb3);
    k_fix<<<(BRv * 128 * Mv) / 256, 256>>>();

    k_gemm<<<dim3(P2 / 64, 4), 256>>>(gpW0, gpb0, p_g,  130, nullptr, 0,   p_A,  P2);
    k_gemm<<<dim3(P2 / 64, 4), 256>>>(gpW1, gpb1, p_A,  256, nullptr, 0,   p_B2, P2);
    k_gemm<<<dim3(P2 / 64, 8), 256>>>(gpW2, gpb2, p_B2, 256, nullptr, 0,   p_C2, P2);
    k_gemm<<<dim3(P2 / 64, 8), 256>>>(gpW3, gpb3, p_g,  130, p_C2,  512,   p_D2, P2);

    k_reduce<<<(Bv * Fv) / 256, 256>>>((float*)d_out);
}

// round 5
// speedup vs baseline: 1.4591x; 1.4591x over previous
#include <cuda_runtime.h>
#include <math.h>

// ---------------- problem constants ----------------
#define Bv   4
#define Rv   4
#define Nv   4096
#define Mv   64
#define KNv  12288
#define BRv  16
#define P1   196608
#define P2   1024
#define Fv   512
#define TILES2 1536          // P1 / 128
#define TPB2   96            // KN / 128 tiles per br

// ---------------- device scratch ----------------
__device__ int   d_topk[Bv * Nv * 3];
__device__ float d_csum[Bv * 2 * Mv];
__device__ float d_ccnt[Bv * Mv];
__device__ float d_nrot[BRv * 2 * Mv];
__device__ float d_g[130 * P2];
__device__ float d_fcol0[BRv * 128];
__device__ float d_A[256 * P2];
__device__ float d_B2[256 * P2];
__device__ float d_C2[512 * P2];
__device__ float d_D2[512 * P2];

// ---------------- packed f32x2 helpers ----------------
__device__ __forceinline__ unsigned long long ffma2(unsigned long long a,
                                                    unsigned long long b,
                                                    unsigned long long c) {
    unsigned long long d;
    asm("fma.rn.f32x2 %0, %1, %2, %3;" : "=l"(d) : "l"(a), "l"(b), "l"(c));
    return d;
}
__device__ __forceinline__ unsigned long long pack2(float lo, float hi) {
    unsigned long long r;
    asm("mov.b64 %0, {%1, %2};" : "=l"(r) : "f"(lo), "f"(hi));
    return r;
}
__device__ __forceinline__ float lo2(unsigned long long a) { return __uint_as_float((unsigned)a); }
__device__ __forceinline__ float hi2(unsigned long long a) { return __uint_as_float((unsigned)(a >> 32)); }

__device__ __forceinline__ void rot_cs(int r, float& c, float& s) {
    float th = 6.2831855f * (float)r * 0.25f;
    c = cosf(th);
    s = sinf(th);
}

// 4-output x 8-col (two contiguous 4-col groups) FFMA2 step
#define STEP4(w, aA, aB, acc)                                                             \
    do {                                                                                  \
        unsigned long long w0d = pack2((w).x, (w).x), w1d = pack2((w).y, (w).y);          \
        unsigned long long w2d = pack2((w).z, (w).z), w3d = pack2((w).w, (w).w);          \
        acc[0][0] = ffma2(w0d, (aA).x, acc[0][0]); acc[0][1] = ffma2(w0d, (aA).y, acc[0][1]); \
        acc[0][2] = ffma2(w0d, (aB).x, acc[0][2]); acc[0][3] = ffma2(w0d, (aB).y, acc[0][3]); \
        acc[1][0] = ffma2(w1d, (aA).x, acc[1][0]); acc[1][1] = ffma2(w1d, (aA).y, acc[1][1]); \
        acc[1][2] = ffma2(w1d, (aB).x, acc[1][2]); acc[1][3] = ffma2(w1d, (aB).y, acc[1][3]); \
        acc[2][0] = ffma2(w2d, (aA).x, acc[2][0]); acc[2][1] = ffma2(w2d, (aA).y, acc[2][1]); \
        acc[2][2] = ffma2(w2d, (aB).x, acc[2][2]); acc[2][3] = ffma2(w2d, (aB).y, acc[2][3]); \
        acc[3][0] = ffma2(w3d, (aA).x, acc[3][0]); acc[3][1] = ffma2(w3d, (aA).y, acc[3][1]); \
        acc[3][2] = ffma2(w3d, (aB).x, acc[3][2]); acc[3][3] = ffma2(w3d, (aB).y, acc[3][3]); \
    } while (0)

// ---------------- K0 ----------------
__global__ void k_init() {
    int i = blockIdx.x * 256 + threadIdx.x;
    if (i < Bv * 2 * Mv) d_csum[i] = 0.f;
    if (i < Bv * Mv)     d_ccnt[i] = 0.f;
    if (i < 130 * P2)    d_g[i]    = 0.f;
}

// ---------------- K1: top-3 + cluster accumulation ----------
__global__ void k_topk(const float* __restrict__ x, const float* __restrict__ node) {
    int idx = blockIdx.x * 256 + threadIdx.x;
    if (idx >= Bv * Nv) return;
    int b = idx >> 12, n = idx & (Nv - 1);
    float x0 = x[b * 2 * Nv + n];
    float x1 = x[b * 2 * Nv + Nv + n];
    float d0 = 3.4e38f, d1 = 3.4e38f, d2 = 3.4e38f;
    int   i0 = 0, i1 = 0, i2 = 0;
    #pragma unroll
    for (int m = 0; m < Mv; m++) {
        float dx = x0 - __ldg(&node[b * 2 * Mv + m]);
        float dy = x1 - __ldg(&node[b * 2 * Mv + Mv + m]);
        float d = dx * dx + dy * dy;
        if (d < d0)      { d2 = d1; i2 = i1; d1 = d0; i1 = i0; d0 = d; i0 = m; }
        else if (d < d1) { d2 = d1; i2 = i1; d1 = d;  i1 = m; }
        else if (d < d2) { d2 = d;  i2 = m; }
    }
    int o = idx * 3;
    d_topk[o] = i0; d_topk[o + 1] = i1; d_topk[o + 2] = i2;
    atomicAdd(&d_csum[b * 2 * Mv + i0],      x0);
    atomicAdd(&d_csum[b * 2 * Mv + Mv + i0], x1);
    atomicAdd(&d_ccnt[b * Mv + i0], 1.f);
    atomicAdd(&d_csum[b * 2 * Mv + i1],      x0);
    atomicAdd(&d_csum[b * 2 * Mv + Mv + i1], x1);
    atomicAdd(&d_ccnt[b * Mv + i1], 1.f);
    atomicAdd(&d_csum[b * 2 * Mv + i2],      x0);
    atomicAdd(&d_csum[b * 2 * Mv + Mv + i2], x1);
    atomicAdd(&d_ccnt[b * Mv + i2], 1.f);
}

// ---------------- K2 ----------------
__global__ void k_nodes() {
    int idx = threadIdx.x;
    int b = idx >> 6, m = idx & 63;
    float cnt = d_ccnt[b * Mv + m];
    float inv = 1.f / (cnt + 1e-5f);
    float m0 = d_csum[b * 2 * Mv + m]      * inv;
    float m1 = d_csum[b * 2 * Mv + Mv + m] * inv;
    #pragma unroll
    for (int r = 0; r < Rv; r++) {
        float c, s; rot_cs(r, c, s);
        float n0 = c * m0 - s * m1;
        float n1 = s * m0 + c * m1;
        int br = b * Rv + r;
        d_nrot[(br * 2 + 0) * Mv + m] = n0;
        d_nrot[(br * 2 + 1) * Mv + m] = n1;
        d_g[0 * P2 + br * Mv + m] = n0;
        d_g[1 * P2 + br * Mv + m] = n1;
    }
}

// ---------------- fused fp block (128-col tiles, 512 threads) --------------
// smem layout (float offsets)
#define SW0  0          // 128
#define SB0  128        // 64
#define SB1  192        // 64
#define SB2  256        // 128
#define SB3  384        // 128
#define SW1  512        // [64k][64o]   -> 4608
#define SXS  4608       // [2][128]     -> 4864
#define SMS  4864       // int[128]     -> 4992
#define SBA  4992       // [64k][128c]  -> 13184
#define SBB  13184      // [64k][128c]  -> 21376
#define SBC  21376      // [64k][128c]  -> 29568
#define SW2  29568      // [64k][128o]  -> 37760
#define SW3  37760      // [130k][128o] -> 54400
#define SMEM_FLOATS 54400

__global__ void __launch_bounds__(512, 1) k_fp(
    const float* __restrict__ x,
    const float* __restrict__ W0, const float* __restrict__ b0,
    const float* __restrict__ W1, const float* __restrict__ b1,
    const float* __restrict__ W2, const float* __restrict__ b2,
    const float* __restrict__ W3, const float* __restrict__ b3)
{
    extern __shared__ float sm[];
    const int tid = threadIdx.x;

    for (int i = tid; i < 128; i += 512) sm[SW0 + i] = W0[i];
    for (int i = tid; i < 64;  i += 512) { sm[SB0 + i] = b0[i]; sm[SB1 + i] = b1[i]; }
    for (int i = tid; i < 128; i += 512) { sm[SB2 + i] = b2[i]; sm[SB3 + i] = b3[i]; }
    for (int i = tid; i < 4096; i += 512) { int o = i & 63,  k = i >> 6; sm[SW1 + k * 64  + o] = W1[o * 64  + k]; }
    for (int i = tid; i < 8192; i += 512) { int o = i & 127, k = i >> 7; sm[SW2 + k * 128 + o] = W2[o * 64  + k]; }
    for (int i = tid; i < 130 * 128; i += 512) { int o = i & 127, k = i >> 7; sm[SW3 + k * 128 + o] = W3[o * 130 + k]; }
    __syncthreads();

    int* ms = (int*)(sm + SMS);
    const int og = tid >> 4;            // 0..31
    const int cg = tid & 15;            // 0..15
    const int pA = cg * 4;              // contiguous 4-col group (cols 0-63)
    const int pB = 64 + cg * 4;         // contiguous 4-col group (cols 64-127)

    for (int t = blockIdx.x; t < TILES2; t += gridDim.x) {
        int br = t / TPB2; int tloc = t - br * TPB2; int kn0 = tloc * 128;
        int b = br >> 2, r = br & 3;

        // ---- P0: xdec prologue ----
        if (tid < 128) {
            int kn = kn0 + tid; int k = kn >> 12; int n = kn & (Nv - 1);
            float x0 = x[b * 2 * Nv + n], x1 = x[b * 2 * Nv + Nv + n];
            float c, s; rot_cs(r, c, s);
            float xr0 = c * x0 - s * x1;
            float xr1 = s * x0 + c * x1;
            int m = d_topk[(b * Nv + n) * 3 + k];
            sm[SXS + tid]       = xr0 - d_nrot[(br * 2 + 0) * Mv + m];
            sm[SXS + 128 + tid] = xr1 - d_nrot[(br * 2 + 1) * Mv + m];
            ms[tid] = m;
        }
        __syncthreads();

        // ---- L0: 64 x 128, K=2 ----
        {
            int o0 = og * 2;
            #pragma unroll
            for (int i = 0; i < 2; i++) {
                int o = o0 + i;
                float w0 = sm[SW0 + o * 2], w1 = sm[SW0 + o * 2 + 1], bb = sm[SB0 + o];
                #pragma unroll
                for (int j = 0; j < 4; j++) {
                    float va = fmaf(w0, sm[SXS + pA + j], fmaf(w1, sm[SXS + 128 + pA + j], bb));
                    float vb = fmaf(w0, sm[SXS + pB + j], fmaf(w1, sm[SXS + 128 + pB + j], bb));
                    sm[SBA + o * 128 + pA + j] = fmaxf(va, 0.f);
                    sm[SBA + o * 128 + pB + j] = fmaxf(vb, 0.f);
                }
            }
        }
        __syncthreads();

        // ---- L1: 64 x 128, K=64 (bA -> bB) ----
        {
            int o0 = og * 2;
            unsigned long long acc[2][4];
            #pragma unroll
            for (int i = 0; i < 2; i++)
                #pragma unroll
                for (int j = 0; j < 4; j++) acc[i][j] = 0ull;
            #pragma unroll 4
            for (int kk = 0; kk < 64; kk++) {
                float2 w = *(const float2*)&sm[SW1 + kk * 64 + o0];
                unsigned long long w0d = pack2(w.x, w.x);
                unsigned long long w1d = pack2(w.y, w.y);
                ulonglong2 aA = *(const ulonglong2*)&sm[SBA + kk * 128 + pA];
                ulonglong2 aB = *(const ulonglong2*)&sm[SBA + kk * 128 + pB];
                acc[0][0] = ffma2(w0d, aA.x, acc[0][0]); acc[0][1] = ffma2(w0d, aA.y, acc[0][1]);
                acc[0][2] = ffma2(w0d, aB.x, acc[0][2]); acc[0][3] = ffma2(w0d, aB.y, acc[0][3]);
                acc[1][0] = ffma2(w1d, aA.x, acc[1][0]); acc[1][1] = ffma2(w1d, aA.y, acc[1][1]);
                acc[1][2] = ffma2(w1d, aB.x, acc[1][2]); acc[1][3] = ffma2(w1d, aB.y, acc[1][3]);
            }
            #pragma unroll
            for (int i = 0; i < 2; i++) {
                int o = o0 + i; float bv = sm[SB1 + o];
                float4 rA, rB;
                rA.x = fmaxf(lo2(acc[i][0]) + bv, 0.f); rA.y = fmaxf(hi2(acc[i][0]) + bv, 0.f);
                rA.z = fmaxf(lo2(acc[i][1]) + bv, 0.f); rA.w = fmaxf(hi2(acc[i][1]) + bv, 0.f);
                rB.x = fmaxf(lo2(acc[i][2]) + bv, 0.f); rB.y = fmaxf(hi2(acc[i][2]) + bv, 0.f);
                rB.z = fmaxf(lo2(acc[i][3]) + bv, 0.f); rB.w = fmaxf(hi2(acc[i][3]) + bv, 0.f);
                *(float4*)&sm[SBB + o * 128 + pA] = rA;
                *(float4*)&sm[SBB + o * 128 + pB] = rB;
            }
        }
        __syncthreads();

        // ---- L2: 128 x 128, K=64 (bB -> bA low / bC high) ----
        {
            int o0 = og * 4;
            unsigned long long acc[4][4];
            #pragma unroll
            for (int i = 0; i < 4; i++)
                #pragma unroll
                for (int j = 0; j < 4; j++) acc[i][j] = 0ull;
            #pragma unroll 4
            for (int kk = 0; kk < 64; kk++) {
                float4 w = *(const float4*)&sm[SW2 + kk * 128 + o0];
                ulonglong2 aA = *(const ulonglong2*)&sm[SBB + kk * 128 + pA];
                ulonglong2 aB = *(const ulonglong2*)&sm[SBB + kk * 128 + pB];
                STEP4(w, aA, aB, acc);
            }
            float* dst = (o0 < 64) ? (sm + SBA + o0 * 128) : (sm + SBC + (o0 - 64) * 128);
            #pragma unroll
            for (int i = 0; i < 4; i++) {
                float bv = sm[SB2 + o0 + i];
                float4 rA, rB;
                rA.x = fmaxf(lo2(acc[i][0]) + bv, 0.f); rA.y = fmaxf(hi2(acc[i][0]) + bv, 0.f);
                rA.z = fmaxf(lo2(acc[i][1]) + bv, 0.f); rA.w = fmaxf(hi2(acc[i][1]) + bv, 0.f);
                rB.x = fmaxf(lo2(acc[i][2]) + bv, 0.f); rB.y = fmaxf(hi2(acc[i][2]) + bv, 0.f);
                rB.z = fmaxf(lo2(acc[i][3]) + bv, 0.f); rB.w = fmaxf(hi2(acc[i][3]) + bv, 0.f);
                *(float4*)&dst[i * 128 + pA] = rA;
                *(float4*)&dst[i * 128 + pB] = rB;
            }
        }
        __syncthreads();

        // ---- L3: 128 x 128, K=130 -> scatter-max ----
        {
            int o0 = og * 4;
            unsigned long long acc[4][4];
            #pragma unroll
            for (int i = 0; i < 4; i++)
                #pragma unroll
                for (int j = 0; j < 4; j++) acc[i][j] = 0ull;
            #pragma unroll
            for (int k = 0; k < 2; k++) {
                float4 w = *(const float4*)&sm[SW3 + k * 128 + o0];
                ulonglong2 aA = *(const ulonglong2*)&sm[SXS + k * 128 + pA];
                ulonglong2 aB = *(const ulonglong2*)&sm[SXS + k * 128 + pB];
                STEP4(w, aA, aB, acc);
            }
            #pragma unroll 4
            for (int kk = 0; kk < 64; kk++) {                  // h3 rows 0-63 in bA
                float4 w = *(const float4*)&sm[SW3 + (2 + kk) * 128 + o0];
                ulonglong2 aA = *(const ulonglong2*)&sm[SBA + kk * 128 + pA];
                ulonglong2 aB = *(const ulonglong2*)&sm[SBA + kk * 128 + pB];
                STEP4(w, aA, aB, acc);
            }
            #pragma unroll 4
            for (int kk = 0; kk < 64; kk++) {                  // h3 rows 64-127 in bC
                float4 w = *(const float4*)&sm[SW3 + (66 + kk) * 128 + o0];
                ulonglong2 aA = *(const ulonglong2*)&sm[SBC + kk * 128 + pA];
                ulonglong2 aB = *(const ulonglong2*)&sm[SBC + kk * 128 + pB];
                STEP4(w, aA, aB, acc);
            }
            // epilogue: bias + relu + scatter-max
            int mA[4], mB[4];
            #pragma unroll
            for (int j = 0; j < 4; j++) { mA[j] = ms[pA + j]; mB[j] = ms[pB + j]; }
            #pragma unroll
            for (int i = 0; i < 4; i++) {
                int o = o0 + i; float bv = sm[SB3 + o];
                unsigned* gp = (unsigned*)&d_g[(2 + o) * P2 + br * Mv];
                #pragma unroll
                for (int j = 0; j < 2; j++) {
                    float vl = fmaxf(lo2(acc[i][j]) + bv, 0.f);
                    float vh = fmaxf(hi2(acc[i][j]) + bv, 0.f);
                    atomicMax(gp + mA[2 * j],     __float_as_uint(vl));
                    atomicMax(gp + mA[2 * j + 1], __float_as_uint(vh));
                    if (tloc == 0 && cg == 0 && j == 0)
                        d_fcol0[br * 128 + o] = vl;   // feat[:, :, 0]
                }
                #pragma unroll
                for (int j = 0; j < 2; j++) {
                    float vl = fmaxf(lo2(acc[i][j + 2]) + bv, 0.f);
                    float vh = fmaxf(hi2(acc[i][j + 2]) + bv, 0.f);
                    atomicMax(gp + mB[2 * j],     __float_as_uint(vl));
                    atomicMax(gp + mB[2 * j + 1], __float_as_uint(vh));
                }
            }
        }
        __syncthreads();
    }
}

// ---------------- K5: empty-cluster fallback ----------------
__global__ void k_fix() {
    int idx = blockIdx.x * 256 + threadIdx.x;
    int m = idx & 63; int c = (idx >> 6) & 127; int br = idx >> 13;
    int b = br >> 2;
    if (d_ccnt[b * Mv + m] == 0.f)
        d_g[(2 + c) * P2 + br * Mv + m] = d_fcol0[br * 128 + c];
}

// ---------------- gp GEMM + bias + ReLU (contiguous-lane FFMA2) ------------
__global__ void __launch_bounds__(256) k_gemm(
    const float* __restrict__ W, const float* __restrict__ bias,
    const float* __restrict__ in1, int C1,
    const float* __restrict__ in2, int C2,
    float* __restrict__ out, int P)
{
    __shared__ __align__(16) float Wsh[16][68];
    __shared__ __align__(16) float Ish[16][68];
    const int C = C1 + C2;
    const int col0 = blockIdx.x * 64, ob0 = blockIdx.y * 64;
    const int tid = threadIdx.x;
    const int o0 = (tid >> 3) * 2;
    const int cg = tid & 7;
    const int pA = cg * 4, pB = 32 + cg * 4;
    unsigned long long acc[2][4];
    #pragma unroll
    for (int i = 0; i < 2; i++)
        #pragma unroll
        for (int j = 0; j < 4; j++) acc[i][j] = 0ull;

    for (int k0 = 0; k0 < C; k0 += 16) {
        #pragma unroll
        for (int q = 0; q < 4; q++) {
            int l = tid * 4 + q; int oo = l >> 4, kk = l & 15;
            int c = k0 + kk;
            Wsh[kk][oo] = (c < C) ? W[(ob0 + oo) * C + c] : 0.f;
        }
        #pragma unroll
        for (int q = 0; q < 4; q++) {
            int l = tid * 4 + q; int kk = l >> 6, cc = l & 63;
            int c = k0 + kk;
            float v = 0.f;
            if (c < C1)      v = in1[c * P + col0 + cc];
            else if (c < C)  v = in2[(c - C1) * P + col0 + cc];
            Ish[kk][cc] = v;
        }
        __syncthreads();
        #pragma unroll
        for (int kk = 0; kk < 16; kk++) {
            float2 w = *(const float2*)&Wsh[kk][o0];
            unsigned long long w0d = pack2(w.x, w.x);
            unsigned long long w1d = pack2(w.y, w.y);
            ulonglong2 aA = *(const ulonglong2*)&Ish[kk][pA];
            ulonglong2 aB = *(const ulonglong2*)&Ish[kk][pB];
            acc[0][0] = ffma2(w0d, aA.x, acc[0][0]); acc[0][1] = ffma2(w0d, aA.y, acc[0][1]);
            acc[0][2] = ffma2(w0d, aB.x, acc[0][2]); acc[0][3] = ffma2(w0d, aB.y, acc[0][3]);
            acc[1][0] = ffma2(w1d, aA.x, acc[1][0]); acc[1][1] = ffma2(w1d, aA.y, acc[1][1]);
            acc[1][2] = ffma2(w1d, aB.x, acc[1][2]); acc[1][3] = ffma2(w1d, aB.y, acc[1][3]);
        }
        __syncthreads();
    }
    #pragma unroll
    for (int i = 0; i < 2; i++) {
        int o = ob0 + o0 + i;
        float bv = bias[o];
        float4 rA, rB;
        rA.x = fmaxf(lo2(acc[i][0]) + bv, 0.f); rA.y = fmaxf(hi2(acc[i][0]) + bv, 0.f);
        rA.z = fmaxf(lo2(acc[i][1]) + bv, 0.f); rA.w = fmaxf(hi2(acc[i][1]) + bv, 0.f);
        rB.x = fmaxf(lo2(acc[i][2]) + bv, 0.f); rB.y = fmaxf(hi2(acc[i][2]) + bv, 0.f);
        rB.z = fmaxf(lo2(acc[i][3]) + bv, 0.f); rB.w = fmaxf(hi2(acc[i][3]) + bv, 0.f);
        *(float4*)&out[o * P + col0 + pA] = rA;
        *(float4*)&out[o * P + col0 + pB] = rB;
    }
}

// ---------------- K6: final max over (r, m) ----------------
__global__ void k_reduce(float* __restrict__ out) {
    int idx = blockIdx.x * 256 + threadIdx.x;
    int b = idx >> 9, f = idx & 511;
    const float* src = &d_D2[f * P2 + b * 256];
    float v = 0.f;
    #pragma unroll 8
    for (int j = 0; j < 256; j++) v = fmaxf(v, src[j]);
    out[b * Fv + f] = v;
}

// ---------------- host launcher ----------------
extern "C" void kernel_launch(void* const* d_in, const int* in_sizes, int n_in,
                              void* d_out, int out_size) {
    const float* x    = (const float*)d_in[0];
    const float* node = (const float*)d_in[2];
    const float* fpW0 = (const float*)d_in[4];  const float* fpb0 = (const float*)d_in[5];
    const float* fpW1 = (const float*)d_in[6];  const float* fpb1 = (const float*)d_in[7];
    const float* fpW2 = (const float*)d_in[8];  const float* fpb2 = (const float*)d_in[9];
    const float* fpW3 = (const float*)d_in[10]; const float* fpb3 = (const float*)d_in[11];
    const float* gpW0 = (const float*)d_in[12]; const float* gpb0 = (const float*)d_in[13];
    const float* gpW1 = (const float*)d_in[14]; const float* gpb1 = (const float*)d_in[15];
    const float* gpW2 = (const float*)d_in[16]; const float* gpb2 = (const float*)d_in[17];
    const float* gpW3 = (const float*)d_in[18]; const float* gpb3 = (const float*)d_in[19];

    float *p_g, *p_A, *p_B2, *p_C2, *p_D2;
    cudaGetSymbolAddress((void**)&p_g,  d_g);
    cudaGetSymbolAddress((void**)&p_A,  d_A);
    cudaGetSymbolAddress((void**)&p_B2, d_B2);
    cudaGetSymbolAddress((void**)&p_C2, d_C2);
    cudaGetSymbolAddress((void**)&p_D2, d_D2);

    cudaFuncSetAttribute(k_fp, cudaFuncAttributeMaxDynamicSharedMemorySize,
                         SMEM_FLOATS * 4);

    k_init<<<(130 * P2 + 255) / 256, 256>>>();
    k_topk<<<(Bv * Nv) / 256, 256>>>(x, node);
    k_nodes<<<1, 256>>>();

    k_fp<<<148, 512, SMEM_FLOATS * 4>>>(x, fpW0, fpb0, fpW1, fpb1,
                                        fpW2, fpb2, fpW3, fpb3);
    k_fix<<<(BRv * 128 * Mv) / 256, 256>>>();

    k_gemm<<<dim3(P2 / 64, 4), 256>>>(gpW0, gpb0, p_g,  130, nullptr, 0,   p_A,  P2);
    k_gemm<<<dim3(P2 / 64, 4), 256>>>(gpW1, gpb1, p_A,  256, nullptr, 0,   p_B2, P2);
    k_gemm<<<dim3(P2 / 64, 8), 256>>>(gpW2, gpb2, p_B2, 256, nullptr, 0,   p_C2, P2);
    k_gemm<<<dim3(P2 / 64, 8), 256>>>(gpW3, gpb3, p_g,  130, p_C2,  512,   p_D2, P2);

    k_reduce<<<(Bv * Fv) / 256, 256>>>((float*)d_out);
}

// round 6
// speedup vs baseline: 1.6738x; 1.1472x over previous
#include <cuda_runtime.h>
#include <math.h>

// ---------------- problem constants ----------------
#define Bv   4
#define Rv   4
#define Nv   4096
#define Mv   64
#define KNv  12288
#define BRv  16
#define P1   196608
#define P2   1024
#define Fv   512
#define TILES2 1536          // P1 / 128
#define TPB2   96            // KN / 128 tiles per br

// ---------------- device scratch ----------------
__device__ int   d_topk[Bv * Nv * 3];
__device__ float d_csum[Bv * 2 * Mv];
__device__ float d_ccnt[Bv * Mv];
__device__ float d_nrot[BRv * 2 * Mv];
__device__ float d_g[130 * P2];
__device__ float d_fcol0[BRv * 128];
__device__ float d_A[256 * P2];
__device__ float d_B2[256 * P2];
__device__ float d_C2[512 * P2];
__device__ float d_D2[512 * P2];

// ---------------- packed f32x2 helpers ----------------
__device__ __forceinline__ unsigned long long ffma2(unsigned long long a,
                                                    unsigned long long b,
                                                    unsigned long long c) {
    unsigned long long d;
    asm("fma.rn.f32x2 %0, %1, %2, %3;" : "=l"(d) : "l"(a), "l"(b), "l"(c));
    return d;
}
__device__ __forceinline__ unsigned long long pack2(float lo, float hi) {
    unsigned long long r;
    asm("mov.b64 %0, {%1, %2};" : "=l"(r) : "f"(lo), "f"(hi));
    return r;
}
__device__ __forceinline__ float lo2(unsigned long long a) { return __uint_as_float((unsigned)a); }
__device__ __forceinline__ float hi2(unsigned long long a) { return __uint_as_float((unsigned)(a >> 32)); }

__device__ __forceinline__ void rot_cs(int r, float& c, float& s) {
    float th = 6.2831855f * (float)r * 0.25f;
    c = cosf(th);
    s = sinf(th);
}

// 8 outputs x 4 cols: weights wA(outs 0-3), wB(outs 4-7); act a = 4 cols (2 f32x2)
#define STEP8(wA, wB, a, acc)                                                            \
    do {                                                                                 \
        unsigned long long w0 = pack2((wA).x, (wA).x), w1 = pack2((wA).y, (wA).y);       \
        unsigned long long w2 = pack2((wA).z, (wA).z), w3 = pack2((wA).w, (wA).w);       \
        unsigned long long w4 = pack2((wB).x, (wB).x), w5 = pack2((wB).y, (wB).y);       \
        unsigned long long w6 = pack2((wB).z, (wB).z), w7 = pack2((wB).w, (wB).w);       \
        acc[0][0] = ffma2(w0, (a).x, acc[0][0]); acc[0][1] = ffma2(w0, (a).y, acc[0][1]); \
        acc[1][0] = ffma2(w1, (a).x, acc[1][0]); acc[1][1] = ffma2(w1, (a).y, acc[1][1]); \
        acc[2][0] = ffma2(w2, (a).x, acc[2][0]); acc[2][1] = ffma2(w2, (a).y, acc[2][1]); \
        acc[3][0] = ffma2(w3, (a).x, acc[3][0]); acc[3][1] = ffma2(w3, (a).y, acc[3][1]); \
        acc[4][0] = ffma2(w4, (a).x, acc[4][0]); acc[4][1] = ffma2(w4, (a).y, acc[4][1]); \
        acc[5][0] = ffma2(w5, (a).x, acc[5][0]); acc[5][1] = ffma2(w5, (a).y, acc[5][1]); \
        acc[6][0] = ffma2(w6, (a).x, acc[6][0]); acc[6][1] = ffma2(w6, (a).y, acc[6][1]); \
        acc[7][0] = ffma2(w7, (a).x, acc[7][0]); acc[7][1] = ffma2(w7, (a).y, acc[7][1]); \
    } while (0)

// ---------------- K0 ----------------
__global__ void k_init() {
    int i = blockIdx.x * 256 + threadIdx.x;
    if (i < Bv * 2 * Mv) d_csum[i] = 0.f;
    if (i < Bv * Mv)     d_ccnt[i] = 0.f;
    if (i < 130 * P2)    d_g[i]    = 0.f;
}

// ---------------- K1: top-3 + cluster accumulation ----------
__global__ void k_topk(const float* __restrict__ x, const float* __restrict__ node) {
    int idx = blockIdx.x * 256 + threadIdx.x;
    if (idx >= Bv * Nv) return;
    int b = idx >> 12, n = idx & (Nv - 1);
    float x0 = x[b * 2 * Nv + n];
    float x1 = x[b * 2 * Nv + Nv + n];
    float d0 = 3.4e38f, d1 = 3.4e38f, d2 = 3.4e38f;
    int   i0 = 0, i1 = 0, i2 = 0;
    #pragma unroll
    for (int m = 0; m < Mv; m++) {
        float dx = x0 - __ldg(&node[b * 2 * Mv + m]);
        float dy = x1 - __ldg(&node[b * 2 * Mv + Mv + m]);
        float d = dx * dx + dy * dy;
        if (d < d0)      { d2 = d1; i2 = i1; d1 = d0; i1 = i0; d0 = d; i0 = m; }
        else if (d < d1) { d2 = d1; i2 = i1; d1 = d;  i1 = m; }
        else if (d < d2) { d2 = d;  i2 = m; }
    }
    int o = idx * 3;
    d_topk[o] = i0; d_topk[o + 1] = i1; d_topk[o + 2] = i2;
    atomicAdd(&d_csum[b * 2 * Mv + i0],      x0);
    atomicAdd(&d_csum[b * 2 * Mv + Mv + i0], x1);
    atomicAdd(&d_ccnt[b * Mv + i0], 1.f);
    atomicAdd(&d_csum[b * 2 * Mv + i1],      x0);
    atomicAdd(&d_csum[b * 2 * Mv + Mv + i1], x1);
    atomicAdd(&d_ccnt[b * Mv + i1], 1.f);
    atomicAdd(&d_csum[b * 2 * Mv + i2],      x0);
    atomicAdd(&d_csum[b * 2 * Mv + Mv + i2], x1);
    atomicAdd(&d_ccnt[b * Mv + i2], 1.f);
}

// ---------------- K2 ----------------
__global__ void k_nodes() {
    int idx = threadIdx.x;
    int b = idx >> 6, m = idx & 63;
    float cnt = d_ccnt[b * Mv + m];
    float inv = 1.f / (cnt + 1e-5f);
    float m0 = d_csum[b * 2 * Mv + m]      * inv;
    float m1 = d_csum[b * 2 * Mv + Mv + m] * inv;
    #pragma unroll
    for (int r = 0; r < Rv; r++) {
        float c, s; rot_cs(r, c, s);
        float n0 = c * m0 - s * m1;
        float n1 = s * m0 + c * m1;
        int br = b * Rv + r;
        d_nrot[(br * 2 + 0) * Mv + m] = n0;
        d_nrot[(br * 2 + 1) * Mv + m] = n1;
        d_g[0 * P2 + br * Mv + m] = n0;
        d_g[1 * P2 + br * Mv + m] = n1;
    }
}

// ---------------- fused fp block (128-col tiles, 512 threads) --------------
// smem layout (float offsets)
#define SW0  0          // 128
#define SB0  128        // 64
#define SB1  192        // 64
#define SB2  256        // 128
#define SB3  384        // 128
#define SW1  512        // [64k][64o]   -> 4608
#define SXS  4608       // [2][128]     -> 4864
#define SMS  4864       // int[128]     -> 4992
#define SBA  4992       // [64k][128c]  -> 13184
#define SBB  13184      // [64k][128c]  -> 21376
#define SBC  21376      // [64k][128c]  -> 29568
#define SW2  29568      // [64k][128o]  -> 37760
#define SW3  37760      // [130k][128o] -> 54400
#define SMEM_FLOATS 54400

__global__ void __launch_bounds__(512, 1) k_fp(
    const float* __restrict__ x,
    const float* __restrict__ W0, const float* __restrict__ b0,
    const float* __restrict__ W1, const float* __restrict__ b1,
    const float* __restrict__ W2, const float* __restrict__ b2,
    const float* __restrict__ W3, const float* __restrict__ b3)
{
    extern __shared__ float sm[];
    const int tid = threadIdx.x;

    for (int i = tid; i < 128; i += 512) sm[SW0 + i] = W0[i];
    for (int i = tid; i < 64;  i += 512) { sm[SB0 + i] = b0[i]; sm[SB1 + i] = b1[i]; }
    for (int i = tid; i < 128; i += 512) { sm[SB2 + i] = b2[i]; sm[SB3 + i] = b3[i]; }
    for (int i = tid; i < 4096; i += 512) { int o = i & 63,  k = i >> 6; sm[SW1 + k * 64  + o] = W1[o * 64  + k]; }
    for (int i = tid; i < 8192; i += 512) { int o = i & 127, k = i >> 7; sm[SW2 + k * 128 + o] = W2[o * 64  + k]; }
    for (int i = tid; i < 130 * 128; i += 512) { int o = i & 127, k = i >> 7; sm[SW3 + k * 128 + o] = W3[o * 130 + k]; }
    __syncthreads();

    int* ms = (int*)(sm + SMS);
    const int og = tid >> 5;            // 0..15  (uniform per warp!)
    const int cg = tid & 31;            // 0..31
    const int p0 = cg * 4;              // 4 contiguous cols per thread

    for (int t = blockIdx.x; t < TILES2; t += gridDim.x) {
        int br = t / TPB2; int tloc = t - br * TPB2; int kn0 = tloc * 128;
        int b = br >> 2, r = br & 3;

        // ---- P0: xdec prologue ----
        if (tid < 128) {
            int kn = kn0 + tid; int k = kn >> 12; int n = kn & (Nv - 1);
            float x0 = x[b * 2 * Nv + n], x1 = x[b * 2 * Nv + Nv + n];
            float c, s; rot_cs(r, c, s);
            float xr0 = c * x0 - s * x1;
            float xr1 = s * x0 + c * x1;
            int m = d_topk[(b * Nv + n) * 3 + k];
            sm[SXS + tid]       = xr0 - d_nrot[(br * 2 + 0) * Mv + m];
            sm[SXS + 128 + tid] = xr1 - d_nrot[(br * 2 + 1) * Mv + m];
            ms[tid] = m;
        }
        __syncthreads();

        // ---- L0: 64 x 128, K=2 (4 outs x 4 cols per thread) ----
        {
            int o0 = og * 4;
            #pragma unroll
            for (int i = 0; i < 4; i++) {
                int o = o0 + i;
                float w0 = sm[SW0 + o * 2], w1 = sm[SW0 + o * 2 + 1], bb = sm[SB0 + o];
                float4 rv;
                rv.x = fmaxf(fmaf(w0, sm[SXS + p0 + 0], fmaf(w1, sm[SXS + 128 + p0 + 0], bb)), 0.f);
                rv.y = fmaxf(fmaf(w0, sm[SXS + p0 + 1], fmaf(w1, sm[SXS + 128 + p0 + 1], bb)), 0.f);
                rv.z = fmaxf(fmaf(w0, sm[SXS + p0 + 2], fmaf(w1, sm[SXS + 128 + p0 + 2], bb)), 0.f);
                rv.w = fmaxf(fmaf(w0, sm[SXS + p0 + 3], fmaf(w1, sm[SXS + 128 + p0 + 3], bb)), 0.f);
                *(float4*)&sm[SBA + o * 128 + p0] = rv;
            }
        }
        __syncthreads();

        // ---- L1: 64 x 128, K=64 (bA -> bB), 4 outs x 4 cols ----
        {
            int o0 = og * 4;
            unsigned long long acc[4][2];
            #pragma unroll
            for (int i = 0; i < 4; i++) { acc[i][0] = 0ull; acc[i][1] = 0ull; }
            #pragma unroll 4
            for (int kk = 0; kk < 64; kk++) {
                float4 w = *(const float4*)&sm[SW1 + kk * 64 + o0];   // warp-uniform
                ulonglong2 a = *(const ulonglong2*)&sm[SBA + kk * 128 + p0];
                unsigned long long w0 = pack2(w.x, w.x), w1 = pack2(w.y, w.y);
                unsigned long long w2 = pack2(w.z, w.z), w3 = pack2(w.w, w.w);
                acc[0][0] = ffma2(w0, a.x, acc[0][0]); acc[0][1] = ffma2(w0, a.y, acc[0][1]);
                acc[1][0] = ffma2(w1, a.x, acc[1][0]); acc[1][1] = ffma2(w1, a.y, acc[1][1]);
                acc[2][0] = ffma2(w2, a.x, acc[2][0]); acc[2][1] = ffma2(w2, a.y, acc[2][1]);
                acc[3][0] = ffma2(w3, a.x, acc[3][0]); acc[3][1] = ffma2(w3, a.y, acc[3][1]);
            }
            #pragma unroll
            for (int i = 0; i < 4; i++) {
                int o = o0 + i; float bv = sm[SB1 + o];
                float4 rv;
                rv.x = fmaxf(lo2(acc[i][0]) + bv, 0.f); rv.y = fmaxf(hi2(acc[i][0]) + bv, 0.f);
                rv.z = fmaxf(lo2(acc[i][1]) + bv, 0.f); rv.w = fmaxf(hi2(acc[i][1]) + bv, 0.f);
                *(float4*)&sm[SBB + o * 128 + p0] = rv;
            }
        }
        __syncthreads();

        // ---- L2: 128 x 128, K=64 (bB -> bA low / bC high), 8 outs x 4 cols ----
        {
            int o0 = og * 8;
            unsigned long long acc[8][2];
            #pragma unroll
            for (int i = 0; i < 8; i++) { acc[i][0] = 0ull; acc[i][1] = 0ull; }
            #pragma unroll 4
            for (int kk = 0; kk < 64; kk++) {
                float4 wA = *(const float4*)&sm[SW2 + kk * 128 + o0];
                float4 wB = *(const float4*)&sm[SW2 + kk * 128 + o0 + 4];
                ulonglong2 a = *(const ulonglong2*)&sm[SBB + kk * 128 + p0];
                STEP8(wA, wB, a, acc);
            }
            float* dst = (o0 < 64) ? (sm + SBA + o0 * 128) : (sm + SBC + (o0 - 64) * 128);
            #pragma unroll
            for (int i = 0; i < 8; i++) {
                float bv = sm[SB2 + o0 + i];
                float4 rv;
                rv.x = fmaxf(lo2(acc[i][0]) + bv, 0.f); rv.y = fmaxf(hi2(acc[i][0]) + bv, 0.f);
                rv.z = fmaxf(lo2(acc[i][1]) + bv, 0.f); rv.w = fmaxf(hi2(acc[i][1]) + bv, 0.f);
                *(float4*)&dst[i * 128 + p0] = rv;
            }
        }
        __syncthreads();

        // ---- L3: 128 x 128, K=130 -> scatter-max, 8 outs x 4 cols ----
        {
            int o0 = og * 8;
            unsigned long long acc[8][2];
            #pragma unroll
            for (int i = 0; i < 8; i++) { acc[i][0] = 0ull; acc[i][1] = 0ull; }
            #pragma unroll
            for (int k = 0; k < 2; k++) {
                float4 wA = *(const float4*)&sm[SW3 + k * 128 + o0];
                float4 wB = *(const float4*)&sm[SW3 + k * 128 + o0 + 4];
                ulonglong2 a = *(const ulonglong2*)&sm[SXS + k * 128 + p0];
                STEP8(wA, wB, a, acc);
            }
            #pragma unroll 4
            for (int kk = 0; kk < 64; kk++) {                  // h3 rows 0-63 in bA
                float4 wA = *(const float4*)&sm[SW3 + (2 + kk) * 128 + o0];
                float4 wB = *(const float4*)&sm[SW3 + (2 + kk) * 128 + o0 + 4];
                ulonglong2 a = *(const ulonglong2*)&sm[SBA + kk * 128 + p0];
                STEP8(wA, wB, a, acc);
            }
            #pragma unroll 4
            for (int kk = 0; kk < 64; kk++) {                  // h3 rows 64-127 in bC
                float4 wA = *(const float4*)&sm[SW3 + (66 + kk) * 128 + o0];
                float4 wB = *(const float4*)&sm[SW3 + (66 + kk) * 128 + o0 + 4];
                ulonglong2 a = *(const ulonglong2*)&sm[SBC + kk * 128 + p0];
                STEP8(wA, wB, a, acc);
            }
            // epilogue: bias + relu + scatter-max
            int mc[4];
            #pragma unroll
            for (int j = 0; j < 4; j++) mc[j] = ms[p0 + j];
            #pragma unroll
            for (int i = 0; i < 8; i++) {
                int o = o0 + i; float bv = sm[SB3 + o];
                unsigned* gp = (unsigned*)&d_g[(2 + o) * P2 + br * Mv];
                float v0 = fmaxf(lo2(acc[i][0]) + bv, 0.f);
                float v1 = fmaxf(hi2(acc[i][0]) + bv, 0.f);
                float v2 = fmaxf(lo2(acc[i][1]) + bv, 0.f);
                float v3 = fmaxf(hi2(acc[i][1]) + bv, 0.f);
                atomicMax(gp + mc[0], __float_as_uint(v0));
                atomicMax(gp + mc[1], __float_as_uint(v1));
                atomicMax(gp + mc[2], __float_as_uint(v2));
                atomicMax(gp + mc[3], __float_as_uint(v3));
                if (tloc == 0 && cg == 0)
                    d_fcol0[br * 128 + o] = v0;   // feat[:, :, 0]
            }
        }
        __syncthreads();
    }
}

// ---------------- K5: empty-cluster fallback ----------------
__global__ void k_fix() {
    int idx = blockIdx.x * 256 + threadIdx.x;
    int m = idx & 63; int c = (idx >> 6) & 127; int br = idx >> 13;
    int b = br >> 2;
    if (d_ccnt[b * Mv + m] == 0.f)
        d_g[(2 + c) * P2 + br * Mv + m] = d_fcol0[br * 128 + c];
}

// ---------------- gp GEMM + bias + ReLU (warp-uniform weights) -------------
__global__ void __launch_bounds__(256) k_gemm(
    const float* __restrict__ W, const float* __restrict__ bias,
    const float* __restrict__ in1, int C1,
    const float* __restrict__ in2, int C2,
    float* __restrict__ out, int P)
{
    __shared__ __align__(16) float Wsh[16][68];
    __shared__ __align__(16) float Ish[16][68];
    const int C = C1 + C2;
    const int col0 = blockIdx.x * 64, ob0 = blockIdx.y * 64;
    const int tid = threadIdx.x;
    const int og = tid >> 5;            // 0..7 (uniform per warp)
    const int cg = tid & 31;
    // 8 outs x 2 cols per thread: outs ob0+og*8.., cols col0+cg*2..
    const int o0 = og * 8, p0 = cg * 2;
    unsigned long long acc[8];
    #pragma unroll
    for (int i = 0; i < 8; i++) acc[i] = 0ull;

    for (int k0 = 0; k0 < C; k0 += 16) {
        #pragma unroll
        for (int q = 0; q < 4; q++) {
            int l = tid * 4 + q; int oo = l >> 4, kk = l & 15;
            int c = k0 + kk;
            Wsh[kk][oo] = (c < C) ? W[(ob0 + oo) * C + c] : 0.f;
        }
        #pragma unroll
        for (int q = 0; q < 4; q++) {
            int l = tid * 4 + q; int kk = l >> 6, cc = l & 63;
            int c = k0 + kk;
            float v = 0.f;
            if (c < C1)      v = in1[c * P + col0 + cc];
            else if (c < C)  v = in2[(c - C1) * P + col0 + cc];
            Ish[kk][cc] = v;
        }
        __syncthreads();
        #pragma unroll
        for (int kk = 0; kk < 16; kk++) {
            float4 wA = *(const float4*)&Wsh[kk][o0];
            float4 wB = *(const float4*)&Wsh[kk][o0 + 4];
            unsigned long long a = *(const unsigned long long*)&Ish[kk][p0];
            acc[0] = ffma2(pack2(wA.x, wA.x), a, acc[0]);
            acc[1] = ffma2(pack2(wA.y, wA.y), a, acc[1]);
            acc[2] = ffma2(pack2(wA.z, wA.z), a, acc[2]);
            acc[3] = ffma2(pack2(wA.w, wA.w), a, acc[3]);
            acc[4] = ffma2(pack2(wB.x, wB.x), a, acc[4]);
            acc[5] = ffma2(pack2(wB.y, wB.y), a, acc[5]);
            acc[6] = ffma2(pack2(wB.z, wB.z), a, acc[6]);
            acc[7] = ffma2(pack2(wB.w, wB.w), a, acc[7]);
        }
        __syncthreads();
    }
    #pragma unroll
    for (int i = 0; i < 8; i++) {
        int o = ob0 + o0 + i;
        float bv = bias[o];
        float vl = fmaxf(lo2(acc[i]) + bv, 0.f);
        float vh = fmaxf(hi2(acc[i]) + bv, 0.f);
        *(float2*)&out[o * P + col0 + p0] = make_float2(vl, vh);
    }
}

// ---------------- K6: final max over (r, m) ----------------
__global__ void k_reduce(float* __restrict__ out) {
    int idx = blockIdx.x * 256 + threadIdx.x;
    int b = idx >> 9, f = idx & 511;
    const float* src = &d_D2[f * P2 + b * 256];
    float v = 0.f;
    #pragma unroll 8
    for (int j = 0; j < 256; j++) v = fmaxf(v, src[j]);
    out[b * Fv + f] = v;
}

// ---------------- host launcher ----------------
extern "C" void kernel_launch(void* const* d_in, const int* in_sizes, int n_in,
                              void* d_out, int out_size) {
    const float* x    = (const float*)d_in[0];
    const float* node = (const float*)d_in[2];
    const float* fpW0 = (const float*)d_in[4];  const float* fpb0 = (const float*)d_in[5];
    const float* fpW1 = (const float*)d_in[6];  const float* fpb1 = (const float*)d_in[7];
    const float* fpW2 = (const float*)d_in[8];  const float* fpb2 = (const float*)d_in[9];
    const float* fpW3 = (const float*)d_in[10]; const float* fpb3 = (const float*)d_in[11];
    const float* gpW0 = (const float*)d_in[12]; const float* gpb0 = (const float*)d_in[13];
    const float* gpW1 = (const float*)d_in[14]; const float* gpb1 = (const float*)d_in[15];
    const float* gpW2 = (const float*)d_in[16]; const float* gpb2 = (const float*)d_in[17];
    const float* gpW3 = (const float*)d_in[18]; const float* gpb3 = (const float*)d_in[19];

    float *p_g, *p_A, *p_B2, *p_C2, *p_D2;
    cudaGetSymbolAddress((void**)&p_g,  d_g);
    cudaGetSymbolAddress((void**)&p_A,  d_A);
    cudaGetSymbolAddress((void**)&p_B2, d_B2);
    cudaGetSymbolAddress((void**)&p_C2, d_C2);
    cudaGetSymbolAddress((void**)&p_D2, d_D2);

    cudaFuncSetAttribute(k_fp, cudaFuncAttributeMaxDynamicSharedMemorySize,
                         SMEM_FLOATS * 4);

    k_init<<<(130 * P2 + 255) / 256, 256>>>();
    k_topk<<<(Bv * Nv) / 256, 256>>>(x, node);
    k_nodes<<<1, 256>>>();

    k_fp<<<148, 512, SMEM_FLOATS * 4>>>(x, fpW0, fpb0, fpW1, fpb1,
                                        fpW2, fpb2, fpW3, fpb3);
    k_fix<<<(BRv * 128 * Mv) / 256, 256>>>();

    k_gemm<<<dim3(P2 / 64, 4), 256>>>(gpW0, gpb0, p_g,  130, nullptr, 0,   p_A,  P2);
    k_gemm<<<dim3(P2 / 64, 4), 256>>>(gpW1, gpb1, p_A,  256, nullptr, 0,   p_B2, P2);
    k_gemm<<<dim3(P2 / 64, 8), 256>>>(gpW2, gpb2, p_B2, 256, nullptr, 0,   p_C2, P2);
    k_gemm<<<dim3(P2 / 64, 8), 256>>>(gpW3, gpb3, p_g,  130, p_C2,  512,   p_D2, P2);

    k_reduce<<<(Bv * Fv) / 256, 256>>>((float*)d_out);
}